// round 11
// baseline (speedup 1.0000x reference)
#include <cuda_runtime.h>
#include <math.h>

// Problem constants
#define T_IN     65536
#define EDGE     27
#define TEXT     65590           // T_IN + 2*EDGE
#define NCH      512             // 32*16 channels
#define LBLK     256
#define NBLK     257             // ceil(65590/256); last block length 54
#define LAST_LEN 54
#define OUTT     16384           // T_IN/4
#define ORD      8

#define TOT_BLKTH (NCH*NBLK)     // 131584 = 1028*128 = 514*256

// ---------------- device scratch (no allocations allowed) ----------------
__device__ float  d_Ff[NBLK*NCH*ORD];     // forward zero-state block-final states
__device__ float  d_Zf[NBLK*NCH*ORD];     // forward block-entry states (true)
__device__ float  d_Fb[NBLK*NCH*ORD];     // backward zero-state block-final states
__device__ float  d_Zb[NBLK*NCH*ORD];     // backward block-entry states (true)
__device__ float  d_yLast[NCH];           // TRUE forward y at last extended sample
__device__ float  d_b[9];
__device__ float  d_a[9];
__device__ double d_zid[8];
__device__ double d_Pd[4][64];            // (A^256)^m, m=0..3 (m=0 -> identity)
__device__ double d_Rd[4][64];            // (A^256)^m * A^54

// ---------------- setup: filter design + matrix tables (double) ----------------
__device__ inline void mm8(double dst[8][8], const double A_[8][8],
                           const double B_[8][8], int tid) {
    if (tid < 64) {
        int i = tid >> 3, j = tid & 7;
        double acc = 0.0;
#pragma unroll
        for (int t = 0; t < 8; t++) acc += A_[i][t] * B_[t][j];
        dst[i][j] = acc;
    }
}

__global__ void bd_setup_kernel() {
    __shared__ double sb[9], sa[9], szi[8];
    __shared__ double A[8][8];
    __shared__ double PW[9][8][8];
    __shared__ double T1[8][8], T2[8][8], M54[8][8], P2m[8][8], P3m[8][8];
    int tid = threadIdx.x;

    if (tid == 0) {
        const double PI = 3.14159265358979323846;
        // Chebyshev-I analog prototype, N=8, rp=0.05 dB
        double eps = sqrt(pow(10.0, 0.005) - 1.0);
        double mu  = asinh(1.0 / eps) / 8.0;
        double sm  = sinh(mu), cm = cosh(mu);
        double prr[8], pii[8];
        for (int k = 0; k < 8; k++) {
            double th = PI * (2.0 * (k + 1) - 1.0) / 16.0;
            prr[k] = -sm * sin(th);
            pii[k] =  cm * cos(th);
        }
        // g = real(prod(-p)) / sqrt(1+eps^2)   (N even)
        double gr = 1.0, gi = 0.0;
        for (int k = 0; k < 8; k++) {
            double xr = -prr[k], xi = -pii[k];
            double nr = gr * xr - gi * xi, ni = gr * xi + gi * xr;
            gr = nr; gi = ni;
        }
        double g = gr / sqrt(1.0 + eps * eps);
        // pre-warp (Wn = 0.2, fs = 2)
        double warped = 4.0 * tan(PI * 0.1);
        for (int k = 0; k < 8; k++) { prr[k] *= warped; pii[k] *= warped; }
        for (int i = 0; i < 8; i++) g *= warped;
        // bilinear: pd = (4+p)/(4-p); gd = g*real(1/prod(4-p))
        double pdr[8], pdi[8];
        double qr = 1.0, qi = 0.0;
        for (int k = 0; k < 8; k++) {
            double dr = 4.0 - prr[k], di = -pii[k];
            double nr = 4.0 + prr[k], ni =  pii[k];
            double d2 = dr * dr + di * di;
            pdr[k] = (nr * dr + ni * di) / d2;
            pdi[k] = (ni * dr - nr * di) / d2;
            double tr = qr * dr - qi * di, ti = qr * di + qi * dr;
            qr = tr; qi = ti;
        }
        double gd = g * qr / (qr * qr + qi * qi);
        // a = real(poly(pd)) via conjugate-pair quadratics (pairs (k,7-k))
        double ac[9]; for (int j = 0; j < 9; j++) ac[j] = 0.0; ac[0] = 1.0;
        int deg = 0;
        for (int pp = 0; pp < 4; pp++) {
            double re = pdr[pp], im = pdi[pp];
            double c1 = -2.0 * re, c0 = re * re + im * im;
            double nc[9]; for (int j = 0; j < 9; j++) nc[j] = 0.0;
            for (int j = 0; j <= deg; j++) {
                nc[j]     += ac[j];
                nc[j + 1] += ac[j] * c1;
                nc[j + 2] += ac[j] * c0;
            }
            deg += 2;
            for (int j = 0; j < 9; j++) ac[j] = nc[j];
        }
        double binom[9] = {1, 8, 28, 56, 70, 56, 28, 8, 1};
        for (int j = 0; j < 9; j++) { sa[j] = ac[j]; sb[j] = gd * binom[j]; }
        // zi: solve (I - Comp^T) zi = b[1:] - a[1:]*b[0]  (Gauss, partial pivot)
        double M[8][9];
        for (int i = 0; i < 8; i++)
            for (int j = 0; j < 9; j++) M[i][j] = 0.0;
        for (int i = 0; i < 8; i++) M[i][i] = 1.0;
        for (int i = 0; i < 8; i++) M[i][0] += sa[i + 1];
        for (int i = 0; i < 7; i++) M[i][i + 1] -= 1.0;
        for (int i = 0; i < 8; i++) M[i][8] = sb[i + 1] - sa[i + 1] * sb[0];
        for (int col = 0; col < 8; col++) {
            int piv = col;
            for (int r = col + 1; r < 8; r++)
                if (fabs(M[r][col]) > fabs(M[piv][col])) piv = r;
            if (piv != col)
                for (int j = 0; j < 9; j++) { double t = M[col][j]; M[col][j] = M[piv][j]; M[piv][j] = t; }
            double dv = M[col][col];
            for (int j = col; j < 9; j++) M[col][j] /= dv;
            for (int r = 0; r < 8; r++) {
                if (r == col) continue;
                double f = M[r][col];
                if (f != 0.0)
                    for (int j = col; j < 9; j++) M[r][j] -= f * M[col][j];
            }
        }
        for (int i = 0; i < 8; i++) szi[i] = M[i][8];
        // state transition matrix (DF2T): A[i][0] = -a[i+1]; A[i][i+1] = 1
        for (int i = 0; i < 8; i++)
            for (int j = 0; j < 8; j++) A[i][j] = 0.0;
        for (int i = 0; i < 8; i++) A[i][0] = -sa[i + 1];
        for (int i = 0; i < 7; i++) A[i][i + 1] = 1.0;
        // export filter constants
        for (int j = 0; j < 9; j++) { d_b[j] = (float)sb[j]; d_a[j] = (float)sa[j]; }
        for (int j = 0; j < 8; j++) d_zid[j] = szi[j];
    }
    __syncthreads();

    if (tid < 64) PW[0][tid >> 3][tid & 7] = A[tid >> 3][tid & 7];
    __syncthreads();
    for (int s = 1; s < 9; s++) {            // PW[s] = A^(2^s)
        mm8(PW[s], PW[s - 1], PW[s - 1], tid);
        __syncthreads();
    }
    // A^54 = A^32 * A^16 * A^4 * A^2
    mm8(T1, PW[5], PW[4], tid); __syncthreads();
    mm8(T2, T1, PW[2], tid);    __syncthreads();
    mm8(M54, T2, PW[1], tid);   __syncthreads();
    // (A^256)^2, ^3
    mm8(P2m, PW[8], PW[8], tid); __syncthreads();
    mm8(P3m, P2m, PW[8], tid);   __syncthreads();

    if (tid < 64) {
        int i = tid >> 3, j = tid & 7;
        d_Pd[0][tid] = (i == j) ? 1.0 : 0.0;
        d_Pd[1][tid] = PW[8][i][j];
        d_Pd[2][tid] = P2m[i][j];
        d_Pd[3][tid] = P3m[i][j];
        d_Rd[0][tid] = M54[i][j];
    }
    __syncthreads();
    mm8(T1, PW[8], M54, tid); __syncthreads();
    if (tid < 64) d_Rd[1][tid] = T1[tid >> 3][tid & 7];
    __syncthreads();
    mm8(T1, P2m, M54, tid); __syncthreads();
    if (tid < 64) d_Rd[2][tid] = T1[tid >> 3][tid & 7];
    __syncthreads();
    mm8(T1, P3m, M54, tid); __syncthreads();
    if (tid < 64) d_Rd[3][tid] = T1[tid >> 3][tid & 7];
}

// ---------------- helpers ----------------
__device__ __forceinline__ float bd_ext(const float* __restrict__ xc, int t) {
    if (t < EDGE) return 2.0f * xc[0] - xc[EDGE - t];
    int u = t - EDGE;
    if (u < T_IN) return xc[u];
    int j = u - T_IN;                       // 0..26
    return 2.0f * xc[T_IN - 1] - xc[T_IN - 2 - j];
}

__device__ __forceinline__ float bd_step(float s[8], const float rb[9],
                                         const float ra[8], float xv) {
    float y = fmaf(rb[0], xv, s[0]);
#pragma unroll
    for (int i = 0; i < 7; i++) {
        float t = fmaf(rb[i + 1], xv, s[i + 1]);
        s[i] = fmaf(-ra[i], y, t);
    }
    s[7] = fmaf(-ra[7], y, rb[8] * xv);
    return y;
}

__device__ __forceinline__ void bd_matvec_accd(const double* __restrict__ Mm,
                                               const double v[8], double z[8]) {
#pragma unroll
    for (int i = 0; i < 8; i++) {
        double acc = 0.0;
#pragma unroll
        for (int j = 0; j < 8; j++) acc += Mm[i * 8 + j] * v[j];
        z[i] += acc;
    }
}

// ---------------- K1f: forward zero-state per block -> final states ----------------
__global__ void bd_k1f_kernel(const float* __restrict__ x) {
    int gid = blockIdx.x * blockDim.x + threadIdx.x;
    if (gid >= TOT_BLKTH) return;
    int c = gid & (NCH - 1);
    int k = gid >> 9;
    float rb[9], ra[8];
#pragma unroll
    for (int j = 0; j < 9; j++) rb[j] = d_b[j];
#pragma unroll
    for (int j = 0; j < 8; j++) ra[j] = d_a[j + 1];
    float s[8];
#pragma unroll
    for (int j = 0; j < 8; j++) s[j] = 0.0f;

    const float* xc = x + (size_t)c * T_IN;
    int t0 = k << 8;
    if (k >= 1 && k <= 255) {
        const float* p = xc + t0 - EDGE;
#pragma unroll 4
        for (int i = 0; i < LBLK; i++) (void)bd_step(s, rb, ra, p[i]);
    } else {
        int Lk = (k == NBLK - 1) ? LAST_LEN : LBLK;
        for (int i = 0; i < Lk; i++) (void)bd_step(s, rb, ra, bd_ext(xc, t0 + i));
    }
    float* F = d_Ff + ((size_t)k * NCH + c) * 8;
#pragma unroll
    for (int j = 0; j < 8; j++) F[j] = s[j];
}

// ---------------- K2f: parallel truncated forward chain (double) ----------------
__global__ void bd_k2f_kernel(const float* __restrict__ x) {
    int gid = blockIdx.x * blockDim.x + threadIdx.x;
    if (gid >= TOT_BLKTH) return;
    int c = gid & (NCH - 1);
    int k = gid >> 9;
    double z[8];
#pragma unroll
    for (int j = 0; j < 8; j++) z[j] = 0.0;
#pragma unroll
    for (int m = 0; m < 4; m++) {
        int idx = k - 1 - m;
        if (idx >= 0) {
            const float* F = d_Ff + ((size_t)idx * NCH + c) * 8;
            double v[8];
#pragma unroll
            for (int j = 0; j < 8; j++) v[j] = (double)F[j];
            if (m == 0) {
#pragma unroll
                for (int j = 0; j < 8; j++) z[j] += v[j];
            } else {
                bd_matvec_accd(d_Pd[m], v, z);
            }
        }
    }
    if (k <= 3) {                     // initial-state term (zi * ext0)
        const float* xc = x + (size_t)c * T_IN;
        double e0 = 2.0 * (double)xc[0] - (double)xc[EDGE];
        double v[8];
#pragma unroll
        for (int j = 0; j < 8; j++) v[j] = d_zid[j] * e0;
        if (k == 0) {
#pragma unroll
            for (int j = 0; j < 8; j++) z[j] += v[j];
        } else {
            bd_matvec_accd(d_Pd[k], v, z);
        }
    }
    float* Z = d_Zf + ((size_t)k * NCH + c) * 8;
#pragma unroll
    for (int j = 0; j < 8; j++) Z[j] = (float)z[j];
}

// ---------------- K1b: fwd refilter (true state) + zero-state backward ----------------
__global__ void bd_k1b_kernel(const float* __restrict__ x) {
    extern __shared__ float ybuf[];        // 128 * LBLK floats
    int tid = threadIdx.x;
    int gid = blockIdx.x * blockDim.x + tid;
    int c = gid & (NCH - 1);
    int k = gid >> 9;
    float rb[9], ra[8];
#pragma unroll
    for (int j = 0; j < 9; j++) rb[j] = d_b[j];
#pragma unroll
    for (int j = 0; j < 8; j++) ra[j] = d_a[j + 1];

    float s[8];
    {
        const float* Z = d_Zf + ((size_t)k * NCH + c) * 8;
#pragma unroll
        for (int j = 0; j < 8; j++) s[j] = Z[j];
    }
    const float* xc = x + (size_t)c * T_IN;
    int t0 = k << 8;
    int Lk = (k == NBLK - 1) ? LAST_LEN : LBLK;
    float* my = ybuf + tid;

    if (k >= 1 && k <= 255) {
        const float* p = xc + t0 - EDGE;
#pragma unroll 4
        for (int i = 0; i < LBLK; i++) my[i * 128] = bd_step(s, rb, ra, p[i]);
    } else {
        for (int i = 0; i < Lk; i++) my[i * 128] = bd_step(s, rb, ra, bd_ext(xc, t0 + i));
    }
    if (k == NBLK - 1) d_yLast[c] = my[(LAST_LEN - 1) * 128];  // true y at ext end

    // backward zero-state over the corrected forward y (reverse order)
#pragma unroll
    for (int j = 0; j < 8; j++) s[j] = 0.0f;
    for (int i = Lk - 1; i >= 0; i--) (void)bd_step(s, rb, ra, my[i * 128]);

    float* F = d_Fb + ((size_t)k * NCH + c) * 8;
#pragma unroll
    for (int j = 0; j < 8; j++) F[j] = s[j];
}

// ---------------- K2b: parallel truncated backward chain (double) ----------------
__global__ void bd_k2b_kernel() {
    int gid = blockIdx.x * blockDim.x + threadIdx.x;
    if (gid >= TOT_BLKTH) return;
    int c = gid & (NCH - 1);
    int k = gid >> 9;
    double yl = (double)d_yLast[c];
    if (k == NBLK - 1) {
        float* Z = d_Zb + ((size_t)k * NCH + c) * 8;
#pragma unroll
        for (int j = 0; j < 8; j++) Z[j] = (float)(d_zid[j] * yl);
        return;
    }
    double z[8];
#pragma unroll
    for (int j = 0; j < 8; j++) z[j] = 0.0;
#pragma unroll
    for (int m = 0; m < 4; m++) {
        int jb = k + 1 + m;
        if (jb <= 255) {
            const float* F = d_Fb + ((size_t)jb * NCH + c) * 8;
            double v[8];
#pragma unroll
            for (int j = 0; j < 8; j++) v[j] = (double)F[j];
            if (m == 0) {
#pragma unroll
                for (int j = 0; j < 8; j++) z[j] += v[j];
            } else {
                bd_matvec_accd(d_Pd[m], v, z);
            }
        }
    }
    int dlast = 255 - k;
    if (dlast <= 3) {                 // terms crossing the short last block
        double v[8];
        const float* F = d_Fb + ((size_t)(NBLK - 1) * NCH + c) * 8;
#pragma unroll
        for (int j = 0; j < 8; j++) v[j] = (double)F[j];
        bd_matvec_accd(d_Pd[dlast], v, z);
#pragma unroll
        for (int j = 0; j < 8; j++) v[j] = d_zid[j] * yl;
        bd_matvec_accd(d_Rd[dlast], v, z);
    }
    float* Z = d_Zb + ((size_t)k * NCH + c) * 8;
#pragma unroll
    for (int j = 0; j < 8; j++) Z[j] = (float)z[j];
}

// ---------------- K3: fwd refilter + TRUE-state backward -> decimated outputs ----------------
__global__ void bd_k3_kernel(const float* __restrict__ x, float* __restrict__ out) {
    extern __shared__ float sm[];
    float* ybuf  = sm;                     // 128 * 256 floats (strided per-thread y)
    float* ybout = sm + 128 * LBLK;        // 128 * 64 floats (per-thread outputs)
    int tid = threadIdx.x;
    int gid = blockIdx.x * blockDim.x + tid;
    int c = gid & (NCH - 1);
    int k = gid >> 9;
    float rb[9], ra[8];
#pragma unroll
    for (int j = 0; j < 9; j++) rb[j] = d_b[j];
#pragma unroll
    for (int j = 0; j < 8; j++) ra[j] = d_a[j + 1];

    float s[8];
    {
        const float* Z = d_Zf + ((size_t)k * NCH + c) * 8;
#pragma unroll
        for (int j = 0; j < 8; j++) s[j] = Z[j];
    }
    const float* xc = x + (size_t)c * T_IN;
    int t0 = k << 8;
    int Lk = (k == NBLK - 1) ? LAST_LEN : LBLK;
    float* my = ybuf + tid;

    if (k >= 1 && k <= 255) {
        const float* p = xc + t0 - EDGE;
#pragma unroll 4
        for (int i = 0; i < LBLK; i++) my[i * 128] = bd_step(s, rb, ra, p[i]);
    } else {
        for (int i = 0; i < Lk; i++) my[i * 128] = bd_step(s, rb, ra, bd_ext(xc, t0 + i));
    }

    // backward pass from TRUE entry state: pure recurrence, no corrections
    {
        const float* Z = d_Zb + ((size_t)k * NCH + c) * 8;
#pragma unroll
        for (int j = 0; j < 8; j++) s[j] = Z[j];
    }
    int u0 = (k == 0) ? 0 : (t0 - 24);     // first decimated u in this block
    float* myo = ybout + tid * 64;
    for (int i = Lk - 1; i >= 0; i--) {
        float y = bd_step(s, rb, ra, my[i * 128]);
        int u = t0 + i - EDGE;
        if (u >= 0 && u < T_IN && !(u & 3))
            myo[(u - u0) >> 2] = y;
    }
    __syncthreads();

    // coalesced output write: rows = 128 channels of this block, cols = decimated time
    int cnt = (k == 0) ? 58 : ((k == NBLK - 1) ? 6 : 64);
    int obase = u0 >> 2;
    int lr = tid >> 6;                      // 0..1
    int lo = tid & 63;                      // 0..63
    if (lo < cnt) {
#pragma unroll 4
        for (int r = lr; r < 128; r += 2) {
            int cc = (blockIdx.x * 128 + r) & (NCH - 1);
            out[(size_t)cc * OUTT + obase + lo] = ybout[r * 64 + lo];
        }
    }
}

// ---------------- launch ----------------
extern "C" void kernel_launch(void* const* d_in, const int* in_sizes, int n_in,
                              void* d_out, int out_size) {
    const float* x = (const float*)d_in[0];
    float* out = (float*)d_out;
    (void)in_sizes; (void)n_in; (void)out_size;

    cudaFuncSetAttribute(bd_k1b_kernel,
                         cudaFuncAttributeMaxDynamicSharedMemorySize, 128 * LBLK * 4);
    cudaFuncSetAttribute(bd_k3_kernel,
                         cudaFuncAttributeMaxDynamicSharedMemorySize, 128 * LBLK * 4 + 128 * 64 * 4);

    bd_setup_kernel<<<1, 64>>>();
    bd_k1f_kernel<<<TOT_BLKTH / 128, 128>>>(x);
    bd_k2f_kernel<<<TOT_BLKTH / 256, 256>>>(x);
    bd_k1b_kernel<<<TOT_BLKTH / 128, 128, 128 * LBLK * 4>>>(x);
    bd_k2b_kernel<<<TOT_BLKTH / 256, 256>>>();
    bd_k3_kernel<<<TOT_BLKTH / 128, 128, 128 * LBLK * 4 + 128 * 64 * 4>>>(x, out);
}